// round 16
// baseline (speedup 1.0000x reference)
#include <cuda_runtime.h>
#include <cstdint>

#define BB 32
#define NN 4096
#define DD 768
#define KK 1024
#define CHUNK 512
#define NCHUNK 8
#define ROWS_PER_BLK 8

typedef unsigned long long u64;

__device__ int g_topk[BB * KK];

// Map float to uint with ascending unsigned order == ascending float order.
__device__ __forceinline__ unsigned f2ord(float f) {
    unsigned u = __float_as_uint(f);
    return (u & 0x80000000u) ? ~u : (u | 0x80000000u);
}

// ---------------------------------------------------------------------------
// Fused sort + rank, ONE CTA PER BATCH (32 CTAs x 1024 threads).
// Thread t holds position tt = t&511 of 4 chunks: threads 0-511 own chunks
// 0-3, threads 512-1023 own chunks 4-7. Composite key
// (ord << 12) | (4095 - idx) => jax.lax.top_k order (value desc, index asc);
// keys strictly distinct.
//  Phase 1: 45-stage bitonic sort of all 8 chunks simultaneously (4-way ILP):
//           j<=16 via shfl_xor, j in {32..256} via smem (one barrier pair
//           serves all 8 chunks). Identical network to R11 (measured-good).
//  Phase 2: all 8 sorted chunks are in smem; rank = own position + sum over
//           the 7 sibling chunks of count(> key) via 9-step binary searches
//           with the saturation fix (count can be 512: add (chunk_min > key)).
//           Two passes of 2 keys bound live registers (14 counters/pass).
//           Ranks are a permutation of 0..4095; write idx iff rank < 1024.
// No global scratch, no extra kernel launch.
// ---------------------------------------------------------------------------
__global__ __launch_bounds__(1024) void sort_rank_kernel(const float* __restrict__ sig) {
    __shared__ u64 sm[NN];                 // 32 KB: 8 chunks x 512 keys
    const int b    = blockIdx.x;
    const int t    = threadIdx.x;
    const int half = t >> 9;               // 0: chunks 0-3, 1: chunks 4-7
    const int tt   = t & 511;              // position within each chunk

    u64 r[4];
    #pragma unroll
    for (int e = 0; e < 4; e++) {
        int g = (4 * half + e) * CHUNK + tt;
        float v = sig[(size_t)b * NN + g];
        r[e] = ((u64)f2ord(v) << 12) | (u64)(4095 - g);
    }

    // ---- Phase 1: bitonic sort (45 stages, 4-way ILP) ----
    #pragma unroll
    for (int k = 2; k <= CHUNK; k <<= 1) {
        #pragma unroll
        for (int j = k >> 1; j > 0; j >>= 1) {
            bool keep_max = (((tt & k) == 0) == ((tt & j) == 0));
            if (j >= 32) {
                __syncthreads();
                #pragma unroll
                for (int e = 0; e < 4; e++)
                    sm[(4 * half + e) * CHUNK + tt] = r[e];
                __syncthreads();
                #pragma unroll
                for (int e = 0; e < 4; e++) {
                    u64 o = sm[(4 * half + e) * CHUNK + (tt ^ j)];
                    r[e] = keep_max ? (r[e] > o ? r[e] : o)
                                    : (r[e] < o ? r[e] : o);
                }
            } else {
                #pragma unroll
                for (int e = 0; e < 4; e++) {
                    u64 o = __shfl_xor_sync(0xffffffffu, r[e], j);
                    r[e] = keep_max ? (r[e] > o ? r[e] : o)
                                    : (r[e] < o ? r[e] : o);
                }
            }
        }
    }

    // publish final sorted chunks
    __syncthreads();
    #pragma unroll
    for (int e = 0; e < 4; e++)
        sm[(4 * half + e) * CHUNK + tt] = r[e];
    __syncthreads();

    // ---- Phase 2: rank each key vs the 7 sibling chunks ----
    #pragma unroll
    for (int pair = 0; pair < 2; pair++) {
        int cnt[2][NCHUNK - 1];
        #pragma unroll
        for (int e2 = 0; e2 < 2; e2++)
            #pragma unroll
            for (int o = 0; o < NCHUNK - 1; o++) cnt[e2][o] = 0;

        #pragma unroll
        for (int s = CHUNK / 2; s >= 1; s >>= 1) {
            #pragma unroll
            for (int e2 = 0; e2 < 2; e2++) {
                int e   = 2 * pair + e2;
                int myc = 4 * half + e;
                u64 key = r[e];
                #pragma unroll
                for (int o = 0; o < NCHUNK - 1; o++) {
                    int oc = o + (o >= myc ? 1 : 0);
                    if (sm[oc * CHUNK + cnt[e2][o] + s - 1] > key) cnt[e2][o] += s;
                }
            }
        }

        #pragma unroll
        for (int e2 = 0; e2 < 2; e2++) {
            int e   = 2 * pair + e2;
            int myc = 4 * half + e;
            u64 key = r[e];
            int rank = tt;                 // own-chunk count = sorted position
            #pragma unroll
            for (int o = 0; o < NCHUNK - 1; o++) {
                int oc = o + (o >= myc ? 1 : 0);
                // saturation fix: whole chunk greater => true count is CHUNK
                rank += cnt[e2][o] + (sm[oc * CHUNK + CHUNK - 1] > key ? 1 : 0);
            }
            if (rank < KK)
                g_topk[b * KK + rank] = 4095 - (int)(key & 0xFFFu);
        }
    }
}

// ---------------------------------------------------------------------------
// Gather (R11 exact + PDL; ~28us wall = ~7.2TB/s effective, ~90% of spec):
// 8 rows/CTA, 192 threads, one float4 column each, MLP=8.
// ---------------------------------------------------------------------------
__global__ __launch_bounds__(192) void gather_kernel(const float4* __restrict__ x,
                                                     float4* __restrict__ out) {
    const int base = blockIdx.x * ROWS_PER_BLK;
    const int tid  = threadIdx.x;

    cudaGridDependencySynchronize();       // sort_rank kernel fully complete

    const float4* srcs[ROWS_PER_BLK];
    #pragma unroll
    for (int r = 0; r < ROWS_PER_BLK; r++) {
        int row = base + r;
        int b   = row / (KK + 1);
        int rr  = row - b * (KK + 1);
        int src_row = (rr == 0) ? 0 : (1 + g_topk[b * KK + rr - 1]);
        srcs[r] = x + ((size_t)b * (NN + 1) + (size_t)src_row) * (DD / 4);
    }

    float4 vals[ROWS_PER_BLK];
    #pragma unroll
    for (int r = 0; r < ROWS_PER_BLK; r++)
        vals[r] = __ldcs(srcs[r] + tid);

    #pragma unroll
    for (int r = 0; r < ROWS_PER_BLK; r++)
        out[(size_t)(base + r) * (DD / 4) + tid] = vals[r];
}

extern "C" void kernel_launch(void* const* d_in, const int* in_sizes, int n_in,
                              void* d_out, int out_size) {
    const float* x   = (const float*)d_in[0];   // [B, N+1, D] fp32
    const float* sig = (const float*)d_in[1];   // [B, N] fp32
    (void)in_sizes; (void)n_in; (void)out_size;

    sort_rank_kernel<<<BB, 1024>>>(sig);

    cudaLaunchAttribute attr[1];
    attr[0].id = cudaLaunchAttributeProgrammaticStreamSerialization;
    attr[0].val.programmaticStreamSerializationAllowed = 1;

    cudaLaunchConfig_t cfg = {};
    cfg.gridDim  = dim3(BB * (KK + 1) / ROWS_PER_BLK);
    cfg.blockDim = dim3(192);
    cfg.stream   = 0;
    cfg.attrs    = attr;
    cfg.numAttrs = 1;
    cudaLaunchKernelEx(&cfg, gather_kernel, (const float4*)x, (float4*)d_out);
}

// round 17
// speedup vs baseline: 1.2070x; 1.2070x over previous
#include <cuda_runtime.h>
#include <cstdint>

#define BB 32
#define NN 4096
#define DD 768
#define KK 1024
#define CHUNK 512
#define NCHUNK 8
#define ROWS_PER_BLK 8
#define MCTA 256                      // merge CTAs at the front of kernel 2
#define GCTA (BB * (KK + 1) / ROWS_PER_BLK)   // 4100 gather CTAs

typedef unsigned long long u64;

__device__ int g_topk[BB * KK];
__device__ u64 g_scratch[BB * NN];
__device__ int g_done[BB];            // per-batch merge completion counters

// Map float to uint with ascending unsigned order == ascending float order.
__device__ __forceinline__ unsigned f2ord(float f) {
    unsigned u = __float_as_uint(f);
    return (u & 0x80000000u) ? ~u : (u | 0x80000000u);
}

// ---------------------------------------------------------------------------
// Kernel 1 (R11 exact, measured 8.2us): CTA (b,c) sorts 512-element chunk c
// of batch b descending by composite key (ord << 12) | (4095 - idx)
// => jax.lax.top_k order (value desc, index asc). Keys strictly distinct.
// Also resets g_done for this replay (stream-ordered, deterministic).
// ---------------------------------------------------------------------------
__global__ __launch_bounds__(512) void sort_chunk_kernel(const float* __restrict__ sig) {
    __shared__ u64 sm[CHUNK];
    const int b = blockIdx.x >> 3;
    const int c = blockIdx.x & 7;
    const int t = threadIdx.x;

    if (blockIdx.x == 0 && t < BB) g_done[t] = 0;

    const int g = c * CHUNK + t;
    float v = sig[(size_t)b * NN + g];
    u64 r = ((u64)f2ord(v) << 12) | (u64)(4095 - g);

    #pragma unroll
    for (int k = 2; k <= CHUNK; k <<= 1) {
        #pragma unroll
        for (int j = k >> 1; j > 0; j >>= 1) {
            bool keep_max = (((t & k) == 0) == ((t & j) == 0));
            u64 o;
            if (j >= 32) {
                __syncthreads();
                sm[t] = r;
                __syncthreads();
                o = sm[t ^ j];
            } else {
                o = __shfl_xor_sync(0xffffffffu, r, j);
            }
            r = keep_max ? (r > o ? r : o) : (r < o ? r : o);
        }
    }

    g_scratch[(size_t)b * NN + g] = r;
}

// ---------------------------------------------------------------------------
// Kernel 2: role-split grid (256 merge CTAs + 4100 gather CTAs, 256 thr).
// Merge CTA (bid<256), batch b chunk c, 2 keys/thread: rank via 7 interleaved
// 9-step binary searches + saturation fix; write g_topk; release g_done[b].
// Gather CTA: acquire-spin until its batch(es) done, then copy 8 rows,
// warp-per-row, 6 coalesced float4 per lane. Per-batch pipelining: batch b's
// copies start as soon as its 8 merge CTAs finish.
// ---------------------------------------------------------------------------
__global__ __launch_bounds__(256) void merge_gather_kernel(const float4* __restrict__ x,
                                                           float4* __restrict__ out) {
    __shared__ u64 sm[(NCHUNK - 1) * CHUNK];   // 28 KB (merge role only)
    const int bid = blockIdx.x;
    const int t   = threadIdx.x;

    cudaGridDependencySynchronize();           // sort kernel fully complete

    if (bid < MCTA) {
        // ---------------- merge role ----------------
        const int b = bid >> 3;
        const int c = bid & 7;
        const u64* base = g_scratch + (size_t)b * NN;

        #pragma unroll
        for (int o = 0; o < NCHUNK - 1; o++) {
            int oc = o + (o >= c ? 1 : 0);
            sm[o * CHUNK + t]       = base[oc * CHUNK + t];
            sm[o * CHUNK + t + 256] = base[oc * CHUNK + t + 256];
        }
        u64 k0 = base[c * CHUNK + t];
        u64 k1 = base[c * CHUNK + t + 256];
        __syncthreads();

        int c0[NCHUNK - 1], c1[NCHUNK - 1];
        #pragma unroll
        for (int o = 0; o < NCHUNK - 1; o++) { c0[o] = 0; c1[o] = 0; }

        #pragma unroll
        for (int s = CHUNK / 2; s >= 1; s >>= 1) {
            #pragma unroll
            for (int o = 0; o < NCHUNK - 1; o++) {
                if (sm[o * CHUNK + c0[o] + s - 1] > k0) c0[o] += s;
                if (sm[o * CHUNK + c1[o] + s - 1] > k1) c1[o] += s;
            }
        }

        int r0 = t, r1 = t + 256;              // own-chunk sorted positions
        #pragma unroll
        for (int o = 0; o < NCHUNK - 1; o++) {
            u64 cmin = sm[o * CHUNK + CHUNK - 1];
            r0 += c0[o] + (cmin > k0 ? 1 : 0);  // saturation fix (count can be 512)
            r1 += c1[o] + (cmin > k1 ? 1 : 0);
        }

        if (r0 < KK) g_topk[b * KK + r0] = 4095 - (int)(k0 & 0xFFFu);
        if (r1 < KK) g_topk[b * KK + r1] = 4095 - (int)(k1 & 0xFFFu);

        __threadfence();                       // release g_topk writes
        __syncthreads();                       // whole CTA done
        if (t == 0) atomicAdd(&g_done[b], 1);
    } else {
        // ---------------- gather role ----------------
        const int base_row = (bid - MCTA) * ROWS_PER_BLK;
        const int b_first  = base_row / (KK + 1);
        const int b_last   = (base_row + ROWS_PER_BLK - 1) / (KK + 1);

        if (t == 0) {
            for (int bb = b_first; bb <= b_last; bb++) {
                int v;
                do {
                    asm volatile("ld.acquire.gpu.global.b32 %0, [%1];"
                                 : "=r"(v) : "l"(&g_done[bb]) : "memory");
                    if (v < NCHUNK) __nanosleep(64);
                } while (v < NCHUNK);
            }
        }
        __syncthreads();                       // spin result visible to CTA

        const int w    = t >> 5;               // warp -> row
        const int lane = t & 31;
        const int row  = base_row + w;
        const int b    = row / (KK + 1);
        const int rr   = row - b * (KK + 1);
        const int src_row = (rr == 0) ? 0 : (1 + g_topk[b * KK + rr - 1]);

        const float4* src = x   + ((size_t)b * (NN + 1) + (size_t)src_row) * (DD / 4);
        float4*       dst = out + (size_t)row * (DD / 4);

        float4 v[6];                            // 192 cols = 32 lanes x 6
        #pragma unroll
        for (int q = 0; q < 6; q++)
            v[q] = __ldcs(src + lane + 32 * q);
        #pragma unroll
        for (int q = 0; q < 6; q++)
            dst[lane + 32 * q] = v[q];
    }
}

extern "C" void kernel_launch(void* const* d_in, const int* in_sizes, int n_in,
                              void* d_out, int out_size) {
    const float* x   = (const float*)d_in[0];   // [B, N+1, D] fp32
    const float* sig = (const float*)d_in[1];   // [B, N] fp32
    (void)in_sizes; (void)n_in; (void)out_size;

    sort_chunk_kernel<<<BB * NCHUNK, CHUNK>>>(sig);

    cudaLaunchAttribute attr[1];
    attr[0].id = cudaLaunchAttributeProgrammaticStreamSerialization;
    attr[0].val.programmaticStreamSerializationAllowed = 1;

    cudaLaunchConfig_t cfg = {};
    cfg.gridDim  = dim3(MCTA + GCTA);
    cfg.blockDim = dim3(256);
    cfg.stream   = 0;
    cfg.attrs    = attr;
    cfg.numAttrs = 1;
    cudaLaunchKernelEx(&cfg, merge_gather_kernel, (const float4*)x, (float4*)d_out);
}